// round 1
// baseline (speedup 1.0000x reference)
#include <cuda_runtime.h>
#include <math.h>

#define NDIM 384
#define C 128
#define NN (NDIM*NDIM)
#define EPS 1e-5f

// Scratch (allocation-free rule: __device__ globals)
__device__ float g_at[(size_t)C * NN];   // a transposed: [c][k][j]
__device__ float g_bt[(size_t)C * NN];   // b transposed: [c][k][i]
__device__ float g_ct[(size_t)C * NN];   // contracted:   [c][i][j]
__device__ float g_gate[(size_t)NN * C]; // sigmoid(gate_o): [r][c]

__device__ __forceinline__ float sigmf(float x) { return 1.f / (1.f + __expf(-x)); }

// Load 128x128 row-major W into smem with row stride 132 (conflict-free, float4-aligned)
__device__ __forceinline__ void load_w(const float* __restrict__ W, float* w_s, int tid) {
#pragma unroll
    for (int it = 0; it < 16; it++) {
        int idx = (tid + it * 256) * 4;      // 0..65532
        int cc = idx >> 7, kk = idx & 127;
        *(float4*)(w_s + cc * 132 + kk) = *(const float4*)(W + idx);
    }
}

// 64x128 tile GEMM: acc[i][jj] = sum_k zn_s[row][k] * W[col][k]
// rows: ty*4+i, cols: tx + 16*jj
template <int ZS>
__device__ __forceinline__ void gemm_tile(const float* __restrict__ zn_s,
                                          const float* __restrict__ w_s,
                                          int tx, int ty, float (&acc)[4][8]) {
#pragma unroll
    for (int i = 0; i < 4; i++)
#pragma unroll
        for (int j = 0; j < 8; j++) acc[i][j] = 0.f;

#pragma unroll 4
    for (int k = 0; k < 128; k += 4) {
        float4 zv[4];
#pragma unroll
        for (int i = 0; i < 4; i++)
            zv[i] = *(const float4*)(zn_s + (ty * 4 + i) * ZS + k);
#pragma unroll
        for (int jj = 0; jj < 8; jj++) {
            float4 wv = *(const float4*)(w_s + (tx + 16 * jj) * 132 + k);
#pragma unroll
            for (int i = 0; i < 4; i++) {
                acc[i][jj] += zv[i].x * wv.x;
                acc[i][jj] += zv[i].y * wv.y;
                acc[i][jj] += zv[i].z * wv.z;
                acc[i][jj] += zv[i].w * wv.w;
            }
        }
    }
}

// combine proj*sigmoid(gate)*mask, transpose via smem, write channel-major
__device__ __forceinline__ void combine_store(
    float (&accP)[4][8], float (&accG)[4][8],
    const float* __restrict__ bp, const float* __restrict__ bg,
    const float* __restrict__ mask, float* tr, float* __restrict__ gout,
    int r0, int tx, int ty, int tid)
{
#pragma unroll
    for (int i = 0; i < 4; i++) {
        int rl = ty * 4 + i;
        float mv = mask[r0 + rl];
#pragma unroll
        for (int jj = 0; jj < 8; jj++) {
            int cc = tx + 16 * jj;
            float p = accP[i][jj] + bp[cc];
            float g = accG[i][jj] + bg[cc];
            tr[cc * 65 + rl] = p * sigmf(g) * mv;
        }
    }
    __syncthreads();
#pragma unroll
    for (int it = 0; it < 32; it++) {
        int idx = tid + it * 256;
        int cc = idx >> 6, rr = idx & 63;
        gout[cc * NN + r0 + rr] = tr[cc * 65 + rr];
    }
}

// Stage 2: fused LayerNorm + 5 linears (proj_a,gate_a,proj_b,gate_b,gate_o)
__global__ void __launch_bounds__(256) k_linear5(
    const float* __restrict__ z, const float* __restrict__ mask,
    const float* __restrict__ lnw, const float* __restrict__ lnb,
    const float* __restrict__ Wpa, const float* __restrict__ bpa,
    const float* __restrict__ Wga, const float* __restrict__ bga,
    const float* __restrict__ Wpb, const float* __restrict__ bpb,
    const float* __restrict__ Wgb, const float* __restrict__ bgb,
    const float* __restrict__ Wgo, const float* __restrict__ bgo)
{
    extern __shared__ float sm[];
    float* zn_s = sm;           // 64*128 = 8192 floats
    float* w_s = sm + 8192;     // 128*132 = 16896 floats (also reused as transpose buffer)
    int tid = threadIdx.x;
    int r0 = blockIdx.x * 64;

    { // load z tile
        const float4* zg = (const float4*)(z + (size_t)r0 * C);
        float4* zs = (float4*)zn_s;
#pragma unroll
        for (int it = 0; it < 8; it++) zs[tid + it * 256] = zg[tid + it * 256];
    }
    __syncthreads();

    { // layernorm in-place: warp per row
        int lane = tid & 31, wid = tid >> 5;
        float4 wv = ((const float4*)lnw)[lane];
        float4 bv = ((const float4*)lnb)[lane];
#pragma unroll
        for (int rr = 0; rr < 8; rr++) {
            int row = wid * 8 + rr;
            float4 v = *(float4*)(zn_s + row * C + lane * 4);
            float s1 = v.x + v.y + v.z + v.w;
            float s2 = v.x * v.x + v.y * v.y + v.z * v.z + v.w * v.w;
#pragma unroll
            for (int o = 16; o; o >>= 1) {
                s1 += __shfl_xor_sync(0xffffffffu, s1, o);
                s2 += __shfl_xor_sync(0xffffffffu, s2, o);
            }
            float m = s1 * (1.f / 128.f);
            float var = fmaxf(s2 * (1.f / 128.f) - m * m, 0.f);
            float rs = rsqrtf(var + EPS);
            v.x = (v.x - m) * rs * wv.x + bv.x;
            v.y = (v.y - m) * rs * wv.y + bv.y;
            v.z = (v.z - m) * rs * wv.z + bv.z;
            v.w = (v.w - m) * rs * wv.w + bv.w;
            *(float4*)(zn_s + row * C + lane * 4) = v;
        }
    }
    __syncthreads();

    int tx = tid & 15, ty = tid >> 4;
    float acc0[4][8], acc1[4][8];

    // a = proj_a * sigmoid(gate_a) * mask  -> g_at [c][r]
    load_w(Wpa, w_s, tid); __syncthreads();
    gemm_tile<128>(zn_s, w_s, tx, ty, acc0); __syncthreads();
    load_w(Wga, w_s, tid); __syncthreads();
    gemm_tile<128>(zn_s, w_s, tx, ty, acc1); __syncthreads();
    combine_store(acc0, acc1, bpa, bga, mask, w_s, g_at, r0, tx, ty, tid);
    __syncthreads();

    // b = proj_b * sigmoid(gate_b) * mask  -> g_bt [c][r]
    load_w(Wpb, w_s, tid); __syncthreads();
    gemm_tile<128>(zn_s, w_s, tx, ty, acc0); __syncthreads();
    load_w(Wgb, w_s, tid); __syncthreads();
    gemm_tile<128>(zn_s, w_s, tx, ty, acc1); __syncthreads();
    combine_store(acc0, acc1, bpb, bgb, mask, w_s, g_bt, r0, tx, ty, tid);
    __syncthreads();

    // gate = sigmoid(gate_o) -> g_gate [r][c]
    load_w(Wgo, w_s, tid); __syncthreads();
    gemm_tile<128>(zn_s, w_s, tx, ty, acc0);
#pragma unroll
    for (int i = 0; i < 4; i++) {
        int r = r0 + ty * 4 + i;
#pragma unroll
        for (int jj = 0; jj < 8; jj++) {
            int cc = tx + 16 * jj;
            g_gate[(size_t)r * C + cc] = sigmf(acc0[i][jj] + bgo[cc]);
        }
    }
}

// Stage 3: per-channel contraction ct[c] = bt[c]^T @ at[c]  (128x128 tile per block)
__global__ void __launch_bounds__(256) k_contract(const float* __restrict__ mask) {
    int tid = threadIdx.x;
    int b = blockIdx.x;
    int bj = b % 3, bi = (b / 3) % 3, c = b / 9;
    const float* __restrict__ A = g_at + c * NN;   // [k][j]
    const float* __restrict__ Bm = g_bt + c * NN;  // [k][i]
    __shared__ float as_[8 * 128];
    __shared__ float bs_[8 * 128];
    int tx = tid & 15, ty = tid >> 4;
    float acc[8][8];
#pragma unroll
    for (int i = 0; i < 8; i++)
#pragma unroll
        for (int j = 0; j < 8; j++) acc[i][j] = 0.f;

    int lrow = tid >> 5;            // 0..7
    int lcol = (tid & 31) * 4;      // 0..124
    int jbase = bj * 128, ibase = bi * 128;

    for (int k0 = 0; k0 < NDIM; k0 += 8) {
        float4 av = *(const float4*)(A + (k0 + lrow) * NDIM + jbase + lcol);
        float4 bv = *(const float4*)(Bm + (k0 + lrow) * NDIM + ibase + lcol);
        __syncthreads();
        *(float4*)(as_ + lrow * 128 + lcol) = av;
        *(float4*)(bs_ + lrow * 128 + lcol) = bv;
        __syncthreads();
#pragma unroll
        for (int kk = 0; kk < 8; kk++) {
            float4 a0 = *(const float4*)(as_ + kk * 128 + tx * 8);
            float4 a1 = *(const float4*)(as_ + kk * 128 + tx * 8 + 4);
            float4 b0 = *(const float4*)(bs_ + kk * 128 + ty * 8);
            float4 b1 = *(const float4*)(bs_ + kk * 128 + ty * 8 + 4);
            float aa[8] = {a0.x, a0.y, a0.z, a0.w, a1.x, a1.y, a1.z, a1.w};
            float bb[8] = {b0.x, b0.y, b0.z, b0.w, b1.x, b1.y, b1.z, b1.w};
#pragma unroll
            for (int ii = 0; ii < 8; ii++)
#pragma unroll
                for (int jj = 0; jj < 8; jj++) acc[ii][jj] += bb[ii] * aa[jj];
        }
    }

    float* __restrict__ O = g_ct + c * NN;
#pragma unroll
    for (int ii = 0; ii < 8; ii++) {
        int ig = ibase + ty * 8 + ii;
        const float* mrow = mask + ig * NDIM + jbase + tx * 8;
        float4 m0 = *(const float4*)(mrow);
        float4 m1 = *(const float4*)(mrow + 4);
        float4 o0 = make_float4(acc[ii][0] * m0.x, acc[ii][1] * m0.y,
                                acc[ii][2] * m0.z, acc[ii][3] * m0.w);
        float4 o1 = make_float4(acc[ii][4] * m1.x, acc[ii][5] * m1.y,
                                acc[ii][6] * m1.z, acc[ii][7] * m1.w);
        *(float4*)(O + ig * NDIM + jbase + tx * 8) = o0;
        *(float4*)(O + ig * NDIM + jbase + tx * 8 + 4) = o1;
    }
}

// Stage 4: transpose ct tile, LayerNorm, proj_o linear, multiply by gate
__global__ void __launch_bounds__(256) k_out(
    const float* __restrict__ lnw, const float* __restrict__ lnb,
    const float* __restrict__ Wo, const float* __restrict__ bo,
    float* __restrict__ out)
{
    extern __shared__ float sm[];
    float* cs = sm;             // 64*132 = 8448 floats
    float* w_s = sm + 8448;     // 128*132 = 16896 floats
    int tid = threadIdx.x;
    int r0 = blockIdx.x * 64;

    // transposed load: ct[c][r0+rr] -> cs[rr][c] (stride 132)
#pragma unroll
    for (int it = 0; it < 8; it++) {
        int idx = (tid + it * 256) * 4;
        int cc = idx >> 6, rr = idx & 63;
        float4 v = *(const float4*)(g_ct + cc * NN + r0 + rr);
        cs[(rr + 0) * 132 + cc] = v.x;
        cs[(rr + 1) * 132 + cc] = v.y;
        cs[(rr + 2) * 132 + cc] = v.z;
        cs[(rr + 3) * 132 + cc] = v.w;
    }
    __syncthreads();

    { // layernorm (ln_out)
        int lane = tid & 31, wid = tid >> 5;
        float4 wv = ((const float4*)lnw)[lane];
        float4 bv = ((const float4*)lnb)[lane];
#pragma unroll
        for (int rr = 0; rr < 8; rr++) {
            int row = wid * 8 + rr;
            float4 v = *(float4*)(cs + row * 132 + lane * 4);
            float s1 = v.x + v.y + v.z + v.w;
            float s2 = v.x * v.x + v.y * v.y + v.z * v.z + v.w * v.w;
#pragma unroll
            for (int o = 16; o; o >>= 1) {
                s1 += __shfl_xor_sync(0xffffffffu, s1, o);
                s2 += __shfl_xor_sync(0xffffffffu, s2, o);
            }
            float m = s1 * (1.f / 128.f);
            float var = fmaxf(s2 * (1.f / 128.f) - m * m, 0.f);
            float rs = rsqrtf(var + EPS);
            v.x = (v.x - m) * rs * wv.x + bv.x;
            v.y = (v.y - m) * rs * wv.y + bv.y;
            v.z = (v.z - m) * rs * wv.z + bv.z;
            v.w = (v.w - m) * rs * wv.w + bv.w;
            *(float4*)(cs + row * 132 + lane * 4) = v;
        }
    }
    __syncthreads();

    int tx = tid & 15, ty = tid >> 4;
    float acc[4][8];
    load_w(Wo, w_s, tid); __syncthreads();
    gemm_tile<132>(cs, w_s, tx, ty, acc);
#pragma unroll
    for (int i = 0; i < 4; i++) {
        int r = r0 + ty * 4 + i;
#pragma unroll
        for (int jj = 0; jj < 8; jj++) {
            int cc = tx + 16 * jj;
            out[(size_t)r * C + cc] = (acc[i][jj] + bo[cc]) * g_gate[(size_t)r * C + cc];
        }
    }
}

extern "C" void kernel_launch(void* const* d_in, const int* in_sizes, int n_in,
                              void* d_out, int out_size) {
    const float* z    = (const float*)d_in[0];
    const float* mask = (const float*)d_in[1];
    const float* lniw = (const float*)d_in[2];
    const float* lnib = (const float*)d_in[3];
    const float* lnow = (const float*)d_in[4];
    const float* lnob = (const float*)d_in[5];
    const float* Wpa  = (const float*)d_in[6];
    const float* bpa  = (const float*)d_in[7];
    const float* Wga  = (const float*)d_in[8];
    const float* bga  = (const float*)d_in[9];
    const float* Wpb  = (const float*)d_in[10];
    const float* bpb  = (const float*)d_in[11];
    const float* Wgb  = (const float*)d_in[12];
    const float* bgb  = (const float*)d_in[13];
    const float* Wgo  = (const float*)d_in[14];
    const float* bgo  = (const float*)d_in[15];
    const float* Wpo  = (const float*)d_in[16];
    const float* bpo  = (const float*)d_in[17];
    float* out = (float*)d_out;

    const int SMEM2 = (8192 + 16896) * 4;   // 100352 B
    const int SMEM4 = (8448 + 16896) * 4;   // 101376 B
    cudaFuncSetAttribute(k_linear5, cudaFuncAttributeMaxDynamicSharedMemorySize, SMEM2);
    cudaFuncSetAttribute(k_out, cudaFuncAttributeMaxDynamicSharedMemorySize, SMEM4);

    k_linear5<<<NN / 64, 256, SMEM2>>>(z, mask, lniw, lnib,
                                       Wpa, bpa, Wga, bga, Wpb, bpb, Wgb, bgb, Wgo, bgo);
    k_contract<<<9 * C, 256>>>(mask);
    k_out<<<NN / 64, 256, SMEM4>>>(lnow, lnob, Wpo, bpo, out);
}